// round 2
// baseline (speedup 1.0000x reference)
#include <cuda_runtime.h>
#include <cstdint>

#define N_NODES_MAX 100000
#define N_EDGES_MAX 600000

// Scratch (device globals — no allocation allowed in kernel_launch)
__device__ __align__(16) float g_agg[(size_t)N_NODES_MAX * 128];  // agg; reused as 'a'
__device__ __align__(16) float g_h1 [(size_t)N_NODES_MAX * 128];  // layer-1 out; reused as 'b'
__device__ __align__(16) float g_h2 [(size_t)N_NODES_MAX * 128];  // layer-2 out
__device__ __align__(16) float g_deg[N_NODES_MAX];                // degree -> inv-degree

// ---------------------------------------------------------------------------
// utility: zero a float buffer (vectorized)
// ---------------------------------------------------------------------------
__global__ void k_zero(float4* __restrict__ p, int n4) {
    int i = blockIdx.x * blockDim.x + threadIdx.x;
    int stride = gridDim.x * blockDim.x;
    float4 z = make_float4(0.f, 0.f, 0.f, 0.f);
    for (; i < n4; i += stride) p[i] = z;
}

// ---------------------------------------------------------------------------
// degree count + inverse   (edge_index is int32: [2, E], row 0 = src, row 1 = dst)
// ---------------------------------------------------------------------------
__global__ void k_deg_count(const int* __restrict__ ei, float* __restrict__ deg,
                            int E, int N) {
    int e = blockIdx.x * blockDim.x + threadIdx.x;
    if (e < E) {
        int d = ei[E + e];
        if ((unsigned)d < (unsigned)N) atomicAdd(&deg[d], 1.0f);
    }
}

__global__ void k_inv_deg(float* __restrict__ deg, int N) {
    int i = blockIdx.x * blockDim.x + threadIdx.x;
    if (i < N) deg[i] = 1.0f / fmaxf(deg[i], 1.0f);
}

// ---------------------------------------------------------------------------
// Edge aggregation: one warp per edge.
//   msg = x[src] + edge_attr[e] @ We + be   (32 -> 128 matvec, fused)
//   atomicAdd into agg[dst]
// Lane owns j = lane*4 .. lane*4+3 (float4-friendly).
// ---------------------------------------------------------------------------
__global__ void k_aggregate(const float* __restrict__ xin,
                            const int* __restrict__ ei,
                            const float* __restrict__ ea,
                            const float* __restrict__ We,   // [32,128]
                            const float* __restrict__ be,   // [128]
                            float* __restrict__ agg,
                            int E, int N) {
    __shared__ float4 Wes[32 * 32];   // 32 k-rows x 32 float4 (=128 floats)
    {
        const float4* W4 = (const float4*)We;
        for (int i = threadIdx.x; i < 32 * 32; i += blockDim.x) Wes[i] = W4[i];
    }
    __syncthreads();

    int lane = threadIdx.x & 31;
    int warp = (blockIdx.x * blockDim.x + threadIdx.x) >> 5;
    int nwarp = (gridDim.x * blockDim.x) >> 5;

    float4 be4 = ((const float4*)be)[lane];

    for (int e = warp; e < E; e += nwarp) {
        int s = ei[e];
        int d = ei[E + e];
        float eav = ea[(size_t)e * 32 + lane];

        float4 m = be4;
        #pragma unroll
        for (int k = 0; k < 32; k++) {
            float a = __shfl_sync(0xffffffffu, eav, k);
            float4 w = Wes[k * 32 + lane];
            m.x = fmaf(a, w.x, m.x);
            m.y = fmaf(a, w.y, m.y);
            m.z = fmaf(a, w.z, m.z);
            m.w = fmaf(a, w.w, m.w);
        }
        if ((unsigned)s < (unsigned)N && (unsigned)d < (unsigned)N) {
            float4 xv = ((const float4*)xin)[(size_t)s * 32 + lane];
            float* dst = &agg[(size_t)d * 128 + lane * 4];
            atomicAdd(dst + 0, m.x + xv.x);
            atomicAdd(dst + 1, m.y + xv.y);
            atomicAdd(dst + 2, m.z + xv.z);
            atomicAdd(dst + 3, m.w + xv.w);
        }
    }
}

// ---------------------------------------------------------------------------
// Node GEMM:  C = act( (A * scaleA?) @ W1 + (B @ W2)? + bias1? + bias2? )
// A,B: [M,128]; W1,W2: [128,128]; C: [M,128].
// BM=64, N=128, BK=16; 256 threads; thread computes 8x4 outputs.
// ---------------------------------------------------------------------------
__global__ void k_node_gemm(const float* __restrict__ A,
                            const float* __restrict__ scaleA,
                            const float* __restrict__ B,
                            const float* __restrict__ W1,
                            const float* __restrict__ W2,
                            const float* __restrict__ bias1,
                            const float* __restrict__ bias2,
                            float* __restrict__ C,
                            int M, int relu) {
    __shared__ float As[16][68];     // transposed A tile [k][m], padded (68*4=272, mult of 16)
    __shared__ float Ws[16][128];

    const int tid = threadIdx.x;
    const int tx  = tid & 31;        // n: j = tx*4
    const int ty  = tid >> 5;        // m: row = ty*8 + mm
    const int m0  = blockIdx.x * 64;

    float acc[8][4];
    #pragma unroll
    for (int i = 0; i < 8; i++)
        #pragma unroll
        for (int j = 0; j < 4; j++) acc[i][j] = 0.f;

    const int ktiles = (B != nullptr) ? 16 : 8;

    for (int kt = 0; kt < ktiles; kt++) {
        const bool second = (kt >= 8);
        const float* Ain = second ? B  : A;
        const float* Win = second ? W2 : W1;
        const int kb = (kt & 7) * 16;

        // load A tile (64x16), transposed into As[k][m]
        #pragma unroll
        for (int i = 0; i < 4; i++) {
            int lin = tid + i * 256;      // 0..1023
            int m = lin >> 4;
            int k = lin & 15;
            int gm = m0 + m;
            float v = 0.f;
            if (gm < M) {
                v = Ain[(size_t)gm * 128 + kb + k];
                if (!second && scaleA) v *= scaleA[gm];
            }
            As[k][m] = v;
        }
        // load W tile (16x128)
        #pragma unroll
        for (int i = 0; i < 8; i++) {
            int lin = tid + i * 256;      // 0..2047
            int k = lin >> 7;
            int j = lin & 127;
            Ws[k][j] = Win[(size_t)(kb + k) * 128 + j];
        }
        __syncthreads();

        #pragma unroll
        for (int k = 0; k < 16; k++) {
            float4 rn = *(const float4*)&Ws[k][tx * 4];
            float rm[8];
            *(float4*)&rm[0] = *(const float4*)&As[k][ty * 8];
            *(float4*)&rm[4] = *(const float4*)&As[k][ty * 8 + 4];
            #pragma unroll
            for (int mm = 0; mm < 8; mm++) {
                acc[mm][0] = fmaf(rm[mm], rn.x, acc[mm][0]);
                acc[mm][1] = fmaf(rm[mm], rn.y, acc[mm][1]);
                acc[mm][2] = fmaf(rm[mm], rn.z, acc[mm][2]);
                acc[mm][3] = fmaf(rm[mm], rn.w, acc[mm][3]);
            }
        }
        __syncthreads();
    }

    // epilogue
    const int j = tx * 4;
    float4 bs = make_float4(0.f, 0.f, 0.f, 0.f);
    if (bias1) {
        bs.x += bias1[j]; bs.y += bias1[j + 1]; bs.z += bias1[j + 2]; bs.w += bias1[j + 3];
    }
    if (bias2) {
        bs.x += bias2[j]; bs.y += bias2[j + 1]; bs.z += bias2[j + 2]; bs.w += bias2[j + 3];
    }
    #pragma unroll
    for (int mm = 0; mm < 8; mm++) {
        int row = m0 + ty * 8 + mm;
        if (row < M) {
            float4 v;
            v.x = acc[mm][0] + bs.x;
            v.y = acc[mm][1] + bs.y;
            v.z = acc[mm][2] + bs.z;
            v.w = acc[mm][3] + bs.w;
            if (relu) {
                v.x = fmaxf(v.x, 0.f); v.y = fmaxf(v.y, 0.f);
                v.z = fmaxf(v.z, 0.f); v.w = fmaxf(v.w, 0.f);
            }
            *(float4*)&C[(size_t)row * 128 + j] = v;
        }
    }
}

// ---------------------------------------------------------------------------
// Final edge predictor: out[e] = relu(a[src] + b[dst]) @ Wp2 + bp2
// (bp1 already folded into a). One warp per edge.
// ---------------------------------------------------------------------------
__global__ void k_edge_final(const float* __restrict__ a,
                             const float* __restrict__ b,
                             const int* __restrict__ ei,
                             const float* __restrict__ Wp2,   // [128,2]
                             const float* __restrict__ bp2,   // [2]
                             float* __restrict__ out,
                             int E, int N) {
    int lane = threadIdx.x & 31;
    int warp = (blockIdx.x * blockDim.x + threadIdx.x) >> 5;
    int nwarp = (gridDim.x * blockDim.x) >> 5;

    // lane's 4 output rows of Wp2: rows j..j+3, each 2 wide -> 8 floats
    float4 w01 = ((const float4*)Wp2)[lane * 2];
    float4 w23 = ((const float4*)Wp2)[lane * 2 + 1];
    float b0 = bp2[0], b1 = bp2[1];

    for (int e = warp; e < E; e += nwarp) {
        int s = ei[e];
        int d = ei[E + e];
        if ((unsigned)s >= (unsigned)N || (unsigned)d >= (unsigned)N) continue;
        float4 av = ((const float4*)a)[(size_t)s * 32 + lane];
        float4 bv = ((const float4*)b)[(size_t)d * 32 + lane];
        float z0 = fmaxf(av.x + bv.x, 0.f);
        float z1 = fmaxf(av.y + bv.y, 0.f);
        float z2 = fmaxf(av.z + bv.z, 0.f);
        float z3 = fmaxf(av.w + bv.w, 0.f);
        float o0 = z0 * w01.x + z1 * w01.z + z2 * w23.x + z3 * w23.z;
        float o1 = z0 * w01.y + z1 * w01.w + z2 * w23.y + z3 * w23.w;
        #pragma unroll
        for (int off = 16; off > 0; off >>= 1) {
            o0 += __shfl_xor_sync(0xffffffffu, o0, off);
            o1 += __shfl_xor_sync(0xffffffffu, o1, off);
        }
        if (lane == 0) {
            float2 r = make_float2(o0 + b0, o1 + b1);
            *(float2*)&out[(size_t)e * 2] = r;
        }
    }
}

// ---------------------------------------------------------------------------
// launch
// ---------------------------------------------------------------------------
extern "C" void kernel_launch(void* const* d_in, const int* in_sizes, int n_in,
                              void* d_out, int out_size) {
    const float* x    = (const float*)d_in[0];
    const int*   ei   = (const int*)d_in[1];     // int32 (JAX x64 disabled)
    const float* ea   = (const float*)d_in[2];
    const float* We1  = (const float*)d_in[3];
    const float* be1  = (const float*)d_in[4];
    const float* Wl1  = (const float*)d_in[5];
    const float* bl1  = (const float*)d_in[6];
    const float* Wr1  = (const float*)d_in[7];
    const float* br1  = (const float*)d_in[8];
    const float* We2  = (const float*)d_in[9];
    const float* be2  = (const float*)d_in[10];
    const float* Wl2  = (const float*)d_in[11];
    const float* bl2  = (const float*)d_in[12];
    const float* Wr2  = (const float*)d_in[13];
    const float* br2  = (const float*)d_in[14];
    const float* Wp1  = (const float*)d_in[15];
    const float* bp1  = (const float*)d_in[16];
    const float* Wp2  = (const float*)d_in[17];
    const float* bp2  = (const float*)d_in[18];
    float*       out  = (float*)d_out;

    const int N = in_sizes[0] / 128;        // nodes
    const int E = in_sizes[2] / 32;         // edges

    float *agg, *h1, *h2, *deg;
    cudaGetSymbolAddress((void**)&agg, g_agg);
    cudaGetSymbolAddress((void**)&h1,  g_h1);
    cudaGetSymbolAddress((void**)&h2,  g_h2);
    cudaGetSymbolAddress((void**)&deg, g_deg);

    const int nfeat4 = (N * 128) / 4;
    const int zgrid  = (nfeat4 + 255) / 256;
    const int egrid  = (E + 7) / 8;              // warp per edge, 8 warps/block
    const int ggrid  = (N + 63) / 64;

    // degrees (recomputed each launch for determinism)
    k_zero<<<(N / 4 + 255) / 256, 256>>>((float4*)deg, N / 4);
    k_deg_count<<<(E + 255) / 256, 256>>>(ei, deg, E, N);
    k_inv_deg<<<(N + 255) / 256, 256>>>(deg, N);

    // ---- layer 1 ----
    k_zero<<<zgrid, 256>>>((float4*)agg, nfeat4);
    k_aggregate<<<egrid, 256>>>(x, ei, ea, We1, be1, agg, E, N);
    k_node_gemm<<<ggrid, 256>>>(agg, deg, x, Wl1, Wr1, bl1, br1, h1, N, 1);

    // ---- layer 2 ----
    k_zero<<<zgrid, 256>>>((float4*)agg, nfeat4);
    k_aggregate<<<egrid, 256>>>(h1, ei, ea, We2, be2, agg, E, N);
    k_node_gemm<<<ggrid, 256>>>(agg, deg, h1, Wl2, Wr2, bl2, br2, h2, N, 1);

    // ---- edge predictor, factored through nodes ----
    // a = h2 @ Wp1[:128,:] + bp1   (into agg buffer)
    // b = h2 @ Wp1[128:,:]         (into h1 buffer)
    k_node_gemm<<<ggrid, 256>>>(h2, nullptr, nullptr, Wp1, nullptr, bp1, nullptr, agg, N, 0);
    k_node_gemm<<<ggrid, 256>>>(h2, nullptr, nullptr, Wp1 + 128 * 128, nullptr, nullptr, nullptr, h1, N, 0);

    k_edge_final<<<egrid, 256>>>(agg, h1, ei, Wp2, bp2, out, E, N);
}

// round 3
// speedup vs baseline: 1.1465x; 1.1465x over previous
#include <cuda_runtime.h>
#include <cstdint>

#define N_NODES_MAX 100000
#define N_EDGES_MAX 600000

// Scratch (device globals — no allocation allowed in kernel_launch)
__device__ __align__(16) float g_agg[(size_t)N_NODES_MAX * 128];  // agg; reused as 'a'
__device__ __align__(16) float g_h1 [(size_t)N_NODES_MAX * 128];  // layer-1 out; reused as 'b'
__device__ __align__(16) float g_h2 [(size_t)N_NODES_MAX * 128];  // layer-2 out
__device__ __align__(16) float g_deg[N_NODES_MAX];                // degree -> inv-degree

// ---------------------------------------------------------------------------
// packed fp32x2 helpers (FFMA2 — only reachable via PTX fma.rn.f32x2)
// ---------------------------------------------------------------------------
typedef unsigned long long u64;

__device__ __forceinline__ u64 pack2(float lo, float hi) {
    u64 r;
    asm("mov.b64 %0, {%1, %2};" : "=l"(r) : "f"(lo), "f"(hi));
    return r;
}
__device__ __forceinline__ u64 fma2(u64 a, u64 b, u64 c) {
    u64 d;
    asm("fma.rn.f32x2 %0, %1, %2, %3;" : "=l"(d) : "l"(a), "l"(b), "l"(c));
    return d;
}
__device__ __forceinline__ float2 unpack2(u64 v) {
    float2 f;
    asm("mov.b64 {%0, %1}, %2;" : "=f"(f.x), "=f"(f.y) : "l"(v));
    return f;
}
__device__ __forceinline__ void red_add_v4(float* p, float a, float b, float c, float d) {
    asm volatile("red.global.add.v4.f32 [%0], {%1, %2, %3, %4};"
                 :: "l"(p), "f"(a), "f"(b), "f"(c), "f"(d) : "memory");
}

// ---------------------------------------------------------------------------
// utility: zero a float buffer (vectorized)
// ---------------------------------------------------------------------------
__global__ void k_zero(float4* __restrict__ p, int n4) {
    int i = blockIdx.x * blockDim.x + threadIdx.x;
    int stride = gridDim.x * blockDim.x;
    float4 z = make_float4(0.f, 0.f, 0.f, 0.f);
    for (; i < n4; i += stride) p[i] = z;
}

// ---------------------------------------------------------------------------
// degree count + inverse   (edge_index int32: [2, E], row 0 = src, row 1 = dst)
// ---------------------------------------------------------------------------
__global__ void k_deg_count(const int* __restrict__ ei, float* __restrict__ deg,
                            int E, int N) {
    int e = blockIdx.x * blockDim.x + threadIdx.x;
    if (e < E) {
        int d = ei[E + e];
        if ((unsigned)d < (unsigned)N) atomicAdd(&deg[d], 1.0f);
    }
}

__global__ void k_inv_deg(float* __restrict__ deg, int N) {
    int i = blockIdx.x * blockDim.x + threadIdx.x;
    if (i < N) deg[i] = 1.0f / fmaxf(deg[i], 1.0f);
}

// ---------------------------------------------------------------------------
// Edge aggregation: one warp per edge (grid-stride over edges).
//   msg = x[src] + edge_attr[e] @ We + be   (32 -> 128 matvec, fused, f32x2)
//   red.global.add.v4 into agg[dst]
// ---------------------------------------------------------------------------
__global__ void k_aggregate(const float* __restrict__ xin,
                            const int* __restrict__ ei,
                            const float* __restrict__ ea,
                            const float* __restrict__ We,   // [32,128]
                            const float* __restrict__ be,   // [128]
                            float* __restrict__ agg,
                            int E, int N) {
    __shared__ __align__(16) float4 Wes[32 * 32];   // 32 k-rows x 32 float4
    {
        const float4* W4 = (const float4*)We;
        for (int i = threadIdx.x; i < 32 * 32; i += blockDim.x) Wes[i] = W4[i];
    }
    __syncthreads();

    int lane = threadIdx.x & 31;
    int warp = (blockIdx.x * blockDim.x + threadIdx.x) >> 5;
    int nwarp = (gridDim.x * blockDim.x) >> 5;

    float4 be4 = ((const float4*)be)[lane];
    u64 be01 = pack2(be4.x, be4.y);
    u64 be23 = pack2(be4.z, be4.w);

    for (int e = warp; e < E; e += nwarp) {
        int s = ei[e];
        int d = ei[E + e];
        float eav = ea[(size_t)e * 32 + lane];

        u64 m01 = be01, m23 = be23;
        #pragma unroll
        for (int k = 0; k < 32; k++) {
            float a = __shfl_sync(0xffffffffu, eav, k);
            u64 aa = pack2(a, a);
            const ulonglong2 w = *(const ulonglong2*)&Wes[k * 32 + lane];
            m01 = fma2(aa, w.x, m01);
            m23 = fma2(aa, w.y, m23);
        }
        if ((unsigned)s < (unsigned)N && (unsigned)d < (unsigned)N) {
            float4 xv = __ldg((const float4*)xin + (size_t)s * 32 + lane);
            float2 a01 = unpack2(m01);
            float2 a23 = unpack2(m23);
            float* dst = &agg[(size_t)d * 128 + lane * 4];
            red_add_v4(dst, a01.x + xv.x, a01.y + xv.y, a23.x + xv.z, a23.y + xv.w);
        }
    }
}

// ---------------------------------------------------------------------------
// Node GEMM:  C = act( (A * scaleA?) @ W1 + (B @ W2)? + bias1? + bias2? )
// A,B: [M,128]; W1,W2: [128,128]; C: [M,128].
// BM=64, N=128, BK=16; 256 threads; thread computes 8x4 outputs via FFMA2
// (accumulators packed along m: acc[p][j] = rows (2p,2p+1) of col tx*4+j).
// ---------------------------------------------------------------------------
__global__ void k_node_gemm(const float* __restrict__ A,
                            const float* __restrict__ scaleA,
                            const float* __restrict__ B,
                            const float* __restrict__ W1,
                            const float* __restrict__ W2,
                            const float* __restrict__ bias1,
                            const float* __restrict__ bias2,
                            float* __restrict__ C,
                            int M, int relu) {
    __shared__ __align__(16) float As[16][68];   // transposed A tile [k][m]
    __shared__ __align__(16) float Ws[16][128];

    const int tid = threadIdx.x;
    const int tx  = tid & 31;        // n: j = tx*4
    const int ty  = tid >> 5;        // m: rows ty*8 .. ty*8+7
    const int m0  = blockIdx.x * 64;

    u64 acc[4][4];
    #pragma unroll
    for (int p = 0; p < 4; p++)
        #pragma unroll
        for (int j = 0; j < 4; j++) acc[p][j] = 0ull;

    const int ktiles = (B != nullptr) ? 16 : 8;

    for (int kt = 0; kt < ktiles; kt++) {
        const bool second = (kt >= 8);
        const float* Ain = second ? B  : A;
        const float* Win = second ? W2 : W1;
        const int kb = (kt & 7) * 16;

        // load A tile (64x16), transposed into As[k][m]
        #pragma unroll
        for (int i = 0; i < 4; i++) {
            int lin = tid + i * 256;      // 0..1023
            int m = lin >> 4;
            int k = lin & 15;
            int gm = m0 + m;
            float v = 0.f;
            if (gm < M) {
                v = Ain[(size_t)gm * 128 + kb + k];
                if (!second && scaleA) v *= scaleA[gm];
            }
            As[k][m] = v;
        }
        // load W tile (16x128)
        #pragma unroll
        for (int i = 0; i < 8; i++) {
            int lin = tid + i * 256;      // 0..2047
            int k = lin >> 7;
            int j = lin & 127;
            Ws[k][j] = Win[(size_t)(kb + k) * 128 + j];
        }
        __syncthreads();

        #pragma unroll
        for (int k = 0; k < 16; k++) {
            const ulonglong2* pm = (const ulonglong2*)&As[k][ty * 8];
            ulonglong2 mA = pm[0];   // rows 0,1 | 2,3
            ulonglong2 mB = pm[1];   // rows 4,5 | 6,7
            float4 rn = *(const float4*)&Ws[k][tx * 4];
            u64 w0 = pack2(rn.x, rn.x);
            u64 w1 = pack2(rn.y, rn.y);
            u64 w2 = pack2(rn.z, rn.z);
            u64 w3 = pack2(rn.w, rn.w);

            acc[0][0] = fma2(mA.x, w0, acc[0][0]);
            acc[0][1] = fma2(mA.x, w1, acc[0][1]);
            acc[0][2] = fma2(mA.x, w2, acc[0][2]);
            acc[0][3] = fma2(mA.x, w3, acc[0][3]);
            acc[1][0] = fma2(mA.y, w0, acc[1][0]);
            acc[1][1] = fma2(mA.y, w1, acc[1][1]);
            acc[1][2] = fma2(mA.y, w2, acc[1][2]);
            acc[1][3] = fma2(mA.y, w3, acc[1][3]);
            acc[2][0] = fma2(mB.x, w0, acc[2][0]);
            acc[2][1] = fma2(mB.x, w1, acc[2][1]);
            acc[2][2] = fma2(mB.x, w2, acc[2][2]);
            acc[2][3] = fma2(mB.x, w3, acc[2][3]);
            acc[3][0] = fma2(mB.y, w0, acc[3][0]);
            acc[3][1] = fma2(mB.y, w1, acc[3][1]);
            acc[3][2] = fma2(mB.y, w2, acc[3][2]);
            acc[3][3] = fma2(mB.y, w3, acc[3][3]);
        }
        __syncthreads();
    }

    // epilogue
    const int j = tx * 4;
    float4 bs = make_float4(0.f, 0.f, 0.f, 0.f);
    if (bias1) {
        bs.x += bias1[j]; bs.y += bias1[j + 1]; bs.z += bias1[j + 2]; bs.w += bias1[j + 3];
    }
    if (bias2) {
        bs.x += bias2[j]; bs.y += bias2[j + 1]; bs.z += bias2[j + 2]; bs.w += bias2[j + 3];
    }
    #pragma unroll
    for (int p = 0; p < 4; p++) {
        float2 c0 = unpack2(acc[p][0]);
        float2 c1 = unpack2(acc[p][1]);
        float2 c2 = unpack2(acc[p][2]);
        float2 c3 = unpack2(acc[p][3]);
        float4 r0 = make_float4(c0.x + bs.x, c1.x + bs.y, c2.x + bs.z, c3.x + bs.w);
        float4 r1 = make_float4(c0.y + bs.x, c1.y + bs.y, c2.y + bs.z, c3.y + bs.w);
        if (relu) {
            r0.x = fmaxf(r0.x, 0.f); r0.y = fmaxf(r0.y, 0.f);
            r0.z = fmaxf(r0.z, 0.f); r0.w = fmaxf(r0.w, 0.f);
            r1.x = fmaxf(r1.x, 0.f); r1.y = fmaxf(r1.y, 0.f);
            r1.z = fmaxf(r1.z, 0.f); r1.w = fmaxf(r1.w, 0.f);
        }
        int row = m0 + ty * 8 + 2 * p;
        if (row < M)     *(float4*)&C[(size_t)row * 128 + j]       = r0;
        if (row + 1 < M) *(float4*)&C[(size_t)(row + 1) * 128 + j] = r1;
    }
}

// ---------------------------------------------------------------------------
// Final edge predictor: out[e] = relu(a[src] + b[dst]) @ Wp2 + bp2
// (bp1 already folded into a). One warp per edge, grid-stride.
// ---------------------------------------------------------------------------
__global__ void k_edge_final(const float* __restrict__ a,
                             const float* __restrict__ b,
                             const int* __restrict__ ei,
                             const float* __restrict__ Wp2,   // [128,2]
                             const float* __restrict__ bp2,   // [2]
                             float* __restrict__ out,
                             int E, int N) {
    int lane = threadIdx.x & 31;
    int warp = (blockIdx.x * blockDim.x + threadIdx.x) >> 5;
    int nwarp = (gridDim.x * blockDim.x) >> 5;

    float4 w01 = ((const float4*)Wp2)[lane * 2];
    float4 w23 = ((const float4*)Wp2)[lane * 2 + 1];
    float b0 = bp2[0], b1 = bp2[1];

    for (int e = warp; e < E; e += nwarp) {
        int s = ei[e];
        int d = ei[E + e];
        if ((unsigned)s >= (unsigned)N || (unsigned)d >= (unsigned)N) continue;
        float4 av = __ldg((const float4*)a + (size_t)s * 32 + lane);
        float4 bv = __ldg((const float4*)b + (size_t)d * 32 + lane);
        float z0 = fmaxf(av.x + bv.x, 0.f);
        float z1 = fmaxf(av.y + bv.y, 0.f);
        float z2 = fmaxf(av.z + bv.z, 0.f);
        float z3 = fmaxf(av.w + bv.w, 0.f);
        float o0 = z0 * w01.x + z1 * w01.z + z2 * w23.x + z3 * w23.z;
        float o1 = z0 * w01.y + z1 * w01.w + z2 * w23.y + z3 * w23.w;
        #pragma unroll
        for (int off = 16; off > 0; off >>= 1) {
            o0 += __shfl_xor_sync(0xffffffffu, o0, off);
            o1 += __shfl_xor_sync(0xffffffffu, o1, off);
        }
        if (lane == 0) {
            float2 r = make_float2(o0 + b0, o1 + b1);
            *(float2*)&out[(size_t)e * 2] = r;
        }
    }
}

// ---------------------------------------------------------------------------
// launch
// ---------------------------------------------------------------------------
extern "C" void kernel_launch(void* const* d_in, const int* in_sizes, int n_in,
                              void* d_out, int out_size) {
    const float* x    = (const float*)d_in[0];
    const int*   ei   = (const int*)d_in[1];     // int32 (JAX x64 disabled)
    const float* ea   = (const float*)d_in[2];
    const float* We1  = (const float*)d_in[3];
    const float* be1  = (const float*)d_in[4];
    const float* Wl1  = (const float*)d_in[5];
    const float* bl1  = (const float*)d_in[6];
    const float* Wr1  = (const float*)d_in[7];
    const float* br1  = (const float*)d_in[8];
    const float* We2  = (const float*)d_in[9];
    const float* be2  = (const float*)d_in[10];
    const float* Wl2  = (const float*)d_in[11];
    const float* bl2  = (const float*)d_in[12];
    const float* Wr2  = (const float*)d_in[13];
    const float* br2  = (const float*)d_in[14];
    const float* Wp1  = (const float*)d_in[15];
    const float* bp1  = (const float*)d_in[16];
    const float* Wp2  = (const float*)d_in[17];
    const float* bp2  = (const float*)d_in[18];
    float*       out  = (float*)d_out;

    const int N = in_sizes[0] / 128;        // nodes
    const int E = in_sizes[2] / 32;         // edges

    float *agg, *h1, *h2, *deg;
    cudaGetSymbolAddress((void**)&agg, g_agg);
    cudaGetSymbolAddress((void**)&h1,  g_h1);
    cudaGetSymbolAddress((void**)&h2,  g_h2);
    cudaGetSymbolAddress((void**)&deg, g_deg);

    const int nfeat4 = (N * 128) / 4;
    const int zgrid  = (nfeat4 + 255) / 256;
    const int agrid  = 2368;                    // grid-stride, 8 warps/block
    const int ggrid  = (N + 63) / 64;

    // degrees (recomputed each launch for determinism)
    k_zero<<<(N / 4 + 255) / 256, 256>>>((float4*)deg, N / 4);
    k_deg_count<<<(E + 255) / 256, 256>>>(ei, deg, E, N);
    k_inv_deg<<<(N + 255) / 256, 256>>>(deg, N);

    // ---- layer 1 ----
    k_zero<<<zgrid, 256>>>((float4*)agg, nfeat4);
    k_aggregate<<<agrid, 256>>>(x, ei, ea, We1, be1, agg, E, N);
    k_node_gemm<<<ggrid, 256>>>(agg, deg, x, Wl1, Wr1, bl1, br1, h1, N, 1);

    // ---- layer 2 ----
    k_zero<<<zgrid, 256>>>((float4*)agg, nfeat4);
    k_aggregate<<<agrid, 256>>>(h1, ei, ea, We2, be2, agg, E, N);
    k_node_gemm<<<ggrid, 256>>>(agg, deg, h1, Wl2, Wr2, bl2, br2, h2, N, 1);

    // ---- edge predictor, factored through nodes ----
    // a = h2 @ Wp1[:128,:] + bp1   (into agg buffer)
    // b = h2 @ Wp1[128:,:]         (into h1 buffer)
    k_node_gemm<<<ggrid, 256>>>(h2, nullptr, nullptr, Wp1, nullptr, bp1, nullptr, agg, N, 0);
    k_node_gemm<<<ggrid, 256>>>(h2, nullptr, nullptr, Wp1 + 128 * 128, nullptr, nullptr, nullptr, h1, N, 0);

    k_edge_final<<<agrid, 256>>>(agg, h1, ei, Wp2, bp2, out, E, N);
}

// round 4
// speedup vs baseline: 1.6717x; 1.4580x over previous
#include <cuda_runtime.h>
#include <cstdint>

#define N_NODES_MAX 100000
#define N_EDGES_MAX 600000

// Scratch (device globals)
__device__ __align__(16) float g_xsum[(size_t)N_NODES_MAX * 128];  // xsum; reused as 'a'
__device__ __align__(16) float g_h1  [(size_t)N_NODES_MAX * 128];  // layer-1 out; reused as 'b'
__device__ __align__(16) float g_h2  [(size_t)N_NODES_MAX * 128];  // layer-2 out
__device__ __align__(16) float g_eagg[(size_t)N_NODES_MAX * 32];   // sum of edge_attr per dst
__device__ __align__(16) float g_inv [N_NODES_MAX];                // 1/max(deg,1)
__device__ __align__(16) float g_degc[N_NODES_MAX];                // deg>0 ? 1 : 0
__device__ __align__(16) float g_P   [2 * 32 * 128];               // We_l @ Wl_l
__device__ __align__(16) float g_bv1 [2 * 128];                    // be_l @ Wl_l
__device__ __align__(16) float g_bv0 [2 * 128];                    // bl_l + br_l

// ---------------------------------------------------------------------------
// packed fp32x2 helpers (FFMA2 — only reachable via PTX fma.rn.f32x2)
// ---------------------------------------------------------------------------
typedef unsigned long long u64;

__device__ __forceinline__ u64 pack2(float lo, float hi) {
    u64 r; asm("mov.b64 %0, {%1, %2};" : "=l"(r) : "f"(lo), "f"(hi)); return r;
}
__device__ __forceinline__ u64 fma2(u64 a, u64 b, u64 c) {
    u64 d; asm("fma.rn.f32x2 %0, %1, %2, %3;" : "=l"(d) : "l"(a), "l"(b), "l"(c)); return d;
}
__device__ __forceinline__ float2 unpack2(u64 v) {
    float2 f; asm("mov.b64 {%0, %1}, %2;" : "=f"(f.x), "=f"(f.y) : "l"(v)); return f;
}
__device__ __forceinline__ void red_add_v4(float* p, float a, float b, float c, float d) {
    asm volatile("red.global.add.v4.f32 [%0], {%1, %2, %3, %4};"
                 :: "l"(p), "f"(a), "f"(b), "f"(c), "f"(d) : "memory");
}

// ---------------------------------------------------------------------------
__global__ void k_zero(float4* __restrict__ p, int n4) {
    int i = blockIdx.x * blockDim.x + threadIdx.x;
    int stride = gridDim.x * blockDim.x;
    float4 z = make_float4(0.f, 0.f, 0.f, 0.f);
    for (; i < n4; i += stride) p[i] = z;
}

__global__ void k_deg_count(const int* __restrict__ ei, float* __restrict__ deg,
                            int E, int N) {
    int e = blockIdx.x * blockDim.x + threadIdx.x;
    if (e < E) {
        int d = ei[E + e];
        if ((unsigned)d < (unsigned)N) atomicAdd(&deg[d], 1.0f);
    }
}

__global__ void k_inv_transform(float* __restrict__ inv, float* __restrict__ degc, int N) {
    int i = blockIdx.x * blockDim.x + threadIdx.x;
    if (i < N) {
        float raw = inv[i];
        degc[i] = raw > 0.f ? 1.f : 0.f;
        inv[i] = 1.f / fmaxf(raw, 1.f);
    }
}

// ---------------------------------------------------------------------------
// eagg[dst] += edge_attr[e]  (32 floats). One warp handles 4 edges (8 lanes each).
// ---------------------------------------------------------------------------
__global__ void k_eagg(const int* __restrict__ ei, const float* __restrict__ ea,
                       float* __restrict__ eagg, int E, int N) {
    int lane = threadIdx.x & 31;
    int warp = (blockIdx.x * blockDim.x + threadIdx.x) >> 5;
    int nwarp = (gridDim.x * blockDim.x) >> 5;
    int sub = lane >> 3;         // 0..3  edge within warp group
    int q   = lane & 7;          // float4 index 0..7

    const float4* ea4 = (const float4*)ea;
    for (int base = warp * 4; base < E; base += nwarp * 4) {
        int e = base + sub;
        if (e < E) {
            int d = ei[E + e];
            if ((unsigned)d < (unsigned)N) {
                float4 v = __ldg(ea4 + (size_t)e * 8 + q);
                red_add_v4(&eagg[(size_t)d * 32 + q * 4], v.x, v.y, v.z, v.w);
            }
        }
    }
}

// ---------------------------------------------------------------------------
// xsum[dst] += x[src]  (128 floats). One warp per edge, lane owns a float4.
// ---------------------------------------------------------------------------
__global__ void k_xsum(const float* __restrict__ x, const int* __restrict__ ei,
                       float* __restrict__ xsum, int E, int N) {
    int lane = threadIdx.x & 31;
    int warp = (blockIdx.x * blockDim.x + threadIdx.x) >> 5;
    int nwarp = (gridDim.x * blockDim.x) >> 5;

    const float4* x4 = (const float4*)x;
    for (int e = warp; e < E; e += nwarp) {
        int s = ei[e];
        int d = ei[E + e];
        if ((unsigned)s < (unsigned)N && (unsigned)d < (unsigned)N) {
            float4 v = __ldg(x4 + (size_t)s * 32 + lane);
            red_add_v4(&xsum[(size_t)d * 128 + lane * 4], v.x, v.y, v.z, v.w);
        }
    }
}

// ---------------------------------------------------------------------------
// Precompute P_l = We_l @ Wl_l  [32,128], bv1_l = be_l @ Wl_l, bv0_l = bl_l + br_l.
// 2 blocks (one per layer), 128 threads (one per output column).
// ---------------------------------------------------------------------------
__global__ void k_precompute(const float* We1, const float* be1, const float* Wl1,
                             const float* bl1, const float* br1,
                             const float* We2, const float* be2, const float* Wl2,
                             const float* bl2, const float* br2,
                             float* P, float* bv1, float* bv0) {
    int l = blockIdx.x;
    int j = threadIdx.x;
    const float* We = l ? We2 : We1;
    const float* be = l ? be2 : be1;
    const float* Wl = l ? Wl2 : Wl1;
    const float* bl = l ? bl2 : bl1;
    const float* br = l ? br2 : br1;

    for (int i = 0; i < 32; i++) {
        float acc = 0.f;
        for (int k = 0; k < 128; k++) acc = fmaf(We[i * 128 + k], Wl[k * 128 + j], acc);
        P[l * 4096 + i * 128 + j] = acc;
    }
    float a1 = 0.f;
    for (int k = 0; k < 128; k++) a1 = fmaf(be[k], Wl[k * 128 + j], a1);
    bv1[l * 128 + j] = a1;
    bv0[l * 128 + j] = bl[j] + br[j];
}

// ---------------------------------------------------------------------------
// SAGE node GEMM:
//   C = act( inv[m]*(A1 @ W1) + inv[m]*(A2 @ P) + B @ W2 + bv0 + degc[m]*bv1 )
// A1:[M,128] A2:[M,32] B:[M,128]  W1:[128,128] P:[32,128] W2:[128,128]
// A2/B/bv*/inv/degc nullable. BM=64, 256 threads, FFMA2 mainloop.
// ---------------------------------------------------------------------------
__global__ void k_gemm_sage(const float* __restrict__ A1,
                            const float* __restrict__ A2,
                            const float* __restrict__ B,
                            const float* __restrict__ W1,
                            const float* __restrict__ P,
                            const float* __restrict__ W2,
                            const float* __restrict__ bv0,
                            const float* __restrict__ bv1,
                            const float* __restrict__ inv,
                            const float* __restrict__ degc,
                            float* __restrict__ C,
                            int M, int relu) {
    __shared__ __align__(16) float As[16][68];
    __shared__ __align__(16) float Ws[16][128];

    const int tid = threadIdx.x;
    const int tx  = tid & 31;
    const int ty  = tid >> 5;
    const int m0  = blockIdx.x * 64;

    u64 acc[4][4];
    #pragma unroll
    for (int p = 0; p < 4; p++)
        #pragma unroll
        for (int j = 0; j < 4; j++) acc[p][j] = 0ull;

    const int ktiles = (A2 != nullptr) ? 18 : 8;

    for (int kt = 0; kt < ktiles; kt++) {
        const float* Ain;
        const float* Win;
        int kb, astride;
        bool scaled;
        if (kt < 8)       { Ain = A1; Win = W1; kb = kt * 16;        astride = 128; scaled = (inv != nullptr); }
        else if (kt < 10) { Ain = A2; Win = P;  kb = (kt - 8) * 16;  astride = 32;  scaled = (inv != nullptr); }
        else              { Ain = B;  Win = W2; kb = (kt - 10) * 16; astride = 128; scaled = false; }

        #pragma unroll
        for (int i = 0; i < 4; i++) {
            int lin = tid + i * 256;
            int m = lin >> 4;
            int k = lin & 15;
            int gm = m0 + m;
            float v = 0.f;
            if (gm < M) {
                v = Ain[(size_t)gm * astride + kb + k];
                if (scaled) v *= inv[gm];
            }
            As[k][m] = v;
        }
        #pragma unroll
        for (int i = 0; i < 8; i++) {
            int lin = tid + i * 256;
            int k = lin >> 7;
            int j = lin & 127;
            Ws[k][j] = Win[(size_t)(kb + k) * 128 + j];
        }
        __syncthreads();

        #pragma unroll
        for (int k = 0; k < 16; k++) {
            const ulonglong2* pm = (const ulonglong2*)&As[k][ty * 8];
            ulonglong2 mA = pm[0];
            ulonglong2 mB = pm[1];
            float4 rn = *(const float4*)&Ws[k][tx * 4];
            u64 w0 = pack2(rn.x, rn.x);
            u64 w1 = pack2(rn.y, rn.y);
            u64 w2 = pack2(rn.z, rn.z);
            u64 w3 = pack2(rn.w, rn.w);

            acc[0][0] = fma2(mA.x, w0, acc[0][0]);
            acc[0][1] = fma2(mA.x, w1, acc[0][1]);
            acc[0][2] = fma2(mA.x, w2, acc[0][2]);
            acc[0][3] = fma2(mA.x, w3, acc[0][3]);
            acc[1][0] = fma2(mA.y, w0, acc[1][0]);
            acc[1][1] = fma2(mA.y, w1, acc[1][1]);
            acc[1][2] = fma2(mA.y, w2, acc[1][2]);
            acc[1][3] = fma2(mA.y, w3, acc[1][3]);
            acc[2][0] = fma2(mB.x, w0, acc[2][0]);
            acc[2][1] = fma2(mB.x, w1, acc[2][1]);
            acc[2][2] = fma2(mB.x, w2, acc[2][2]);
            acc[2][3] = fma2(mB.x, w3, acc[2][3]);
            acc[3][0] = fma2(mB.y, w0, acc[3][0]);
            acc[3][1] = fma2(mB.y, w1, acc[3][1]);
            acc[3][2] = fma2(mB.y, w2, acc[3][2]);
            acc[3][3] = fma2(mB.y, w3, acc[3][3]);
        }
        __syncthreads();
    }

    // epilogue
    const int j = tx * 4;
    float4 bs = make_float4(0.f, 0.f, 0.f, 0.f);
    if (bv0) { bs.x = bv0[j]; bs.y = bv0[j + 1]; bs.z = bv0[j + 2]; bs.w = bv0[j + 3]; }
    float4 b1 = make_float4(0.f, 0.f, 0.f, 0.f);
    if (bv1) { b1.x = bv1[j]; b1.y = bv1[j + 1]; b1.z = bv1[j + 2]; b1.w = bv1[j + 3]; }

    #pragma unroll
    for (int p = 0; p < 4; p++) {
        float2 c0 = unpack2(acc[p][0]);
        float2 c1 = unpack2(acc[p][1]);
        float2 c2 = unpack2(acc[p][2]);
        float2 c3 = unpack2(acc[p][3]);
        int row = m0 + ty * 8 + 2 * p;
        #pragma unroll
        for (int h = 0; h < 2; h++) {
            int r = row + h;
            if (r < M) {
                float coef = (bv1 && degc) ? degc[r] : 0.f;
                float4 v;
                v.x = (h ? c0.y : c0.x) + bs.x + coef * b1.x;
                v.y = (h ? c1.y : c1.x) + bs.y + coef * b1.y;
                v.z = (h ? c2.y : c2.x) + bs.z + coef * b1.z;
                v.w = (h ? c3.y : c3.x) + bs.w + coef * b1.w;
                if (relu) {
                    v.x = fmaxf(v.x, 0.f); v.y = fmaxf(v.y, 0.f);
                    v.z = fmaxf(v.z, 0.f); v.w = fmaxf(v.w, 0.f);
                }
                *(float4*)&C[(size_t)r * 128 + j] = v;
            }
        }
    }
}

// ---------------------------------------------------------------------------
// Final edge predictor: out[e] = relu(a[src] + b[dst]) @ Wp2 + bp2
// ---------------------------------------------------------------------------
__global__ void k_edge_final(const float* __restrict__ a,
                             const float* __restrict__ b,
                             const int* __restrict__ ei,
                             const float* __restrict__ Wp2,
                             const float* __restrict__ bp2,
                             float* __restrict__ out,
                             int E, int N) {
    int lane = threadIdx.x & 31;
    int warp = (blockIdx.x * blockDim.x + threadIdx.x) >> 5;
    int nwarp = (gridDim.x * blockDim.x) >> 5;

    float4 w01 = ((const float4*)Wp2)[lane * 2];
    float4 w23 = ((const float4*)Wp2)[lane * 2 + 1];
    float b0 = bp2[0], b1 = bp2[1];

    for (int e = warp; e < E; e += nwarp) {
        int s = ei[e];
        int d = ei[E + e];
        if ((unsigned)s >= (unsigned)N || (unsigned)d >= (unsigned)N) continue;
        float4 av = __ldg((const float4*)a + (size_t)s * 32 + lane);
        float4 bv = __ldg((const float4*)b + (size_t)d * 32 + lane);
        float z0 = fmaxf(av.x + bv.x, 0.f);
        float z1 = fmaxf(av.y + bv.y, 0.f);
        float z2 = fmaxf(av.z + bv.z, 0.f);
        float z3 = fmaxf(av.w + bv.w, 0.f);
        float o0 = z0 * w01.x + z1 * w01.z + z2 * w23.x + z3 * w23.z;
        float o1 = z0 * w01.y + z1 * w01.w + z2 * w23.y + z3 * w23.w;
        #pragma unroll
        for (int off = 16; off > 0; off >>= 1) {
            o0 += __shfl_xor_sync(0xffffffffu, o0, off);
            o1 += __shfl_xor_sync(0xffffffffu, o1, off);
        }
        if (lane == 0) {
            float2 r = make_float2(o0 + b0, o1 + b1);
            *(float2*)&out[(size_t)e * 2] = r;
        }
    }
}

// ---------------------------------------------------------------------------
extern "C" void kernel_launch(void* const* d_in, const int* in_sizes, int n_in,
                              void* d_out, int out_size) {
    const float* x    = (const float*)d_in[0];
    const int*   ei   = (const int*)d_in[1];     // int32
    const float* ea   = (const float*)d_in[2];
    const float* We1  = (const float*)d_in[3];
    const float* be1  = (const float*)d_in[4];
    const float* Wl1  = (const float*)d_in[5];
    const float* bl1  = (const float*)d_in[6];
    const float* Wr1  = (const float*)d_in[7];
    const float* br1  = (const float*)d_in[8];
    const float* We2  = (const float*)d_in[9];
    const float* be2  = (const float*)d_in[10];
    const float* Wl2  = (const float*)d_in[11];
    const float* bl2  = (const float*)d_in[12];
    const float* Wr2  = (const float*)d_in[13];
    const float* br2  = (const float*)d_in[14];
    const float* Wp1  = (const float*)d_in[15];
    const float* bp1  = (const float*)d_in[16];
    const float* Wp2  = (const float*)d_in[17];
    const float* bp2  = (const float*)d_in[18];
    float*       out  = (float*)d_out;

    const int N = in_sizes[0] / 128;
    const int E = in_sizes[2] / 32;

    float *xsum, *h1, *h2, *eagg, *inv, *degc, *P, *bv1, *bv0;
    cudaGetSymbolAddress((void**)&xsum, g_xsum);
    cudaGetSymbolAddress((void**)&h1,   g_h1);
    cudaGetSymbolAddress((void**)&h2,   g_h2);
    cudaGetSymbolAddress((void**)&eagg, g_eagg);
    cudaGetSymbolAddress((void**)&inv,  g_inv);
    cudaGetSymbolAddress((void**)&degc, g_degc);
    cudaGetSymbolAddress((void**)&P,    g_P);
    cudaGetSymbolAddress((void**)&bv1,  g_bv1);
    cudaGetSymbolAddress((void**)&bv0,  g_bv0);

    const int nfeat4 = (N * 128) / 4;
    const int zgrid  = (nfeat4 + 255) / 256;
    const int agrid  = 2368;
    const int ggrid  = (N + 63) / 64;

    // degrees
    k_zero<<<(N / 4 + 255) / 256, 256>>>((float4*)inv, N / 4);
    k_deg_count<<<(E + 255) / 256, 256>>>(ei, inv, E, N);
    k_inv_transform<<<(N + 255) / 256, 256>>>(inv, degc, N);

    // edge-attr aggregation (once — shared by both layers)
    k_zero<<<(N * 32 / 4 + 255) / 256, 256>>>((float4*)eagg, N * 32 / 4);
    k_eagg<<<agrid, 256>>>(ei, ea, eagg, E, N);

    // weight precompute: P_l = We_l@Wl_l, bv1_l = be_l@Wl_l, bv0_l = bl+br
    k_precompute<<<2, 128>>>(We1, be1, Wl1, bl1, br1, We2, be2, Wl2, bl2, br2, P, bv1, bv0);

    // ---- layer 1 ----
    k_zero<<<zgrid, 256>>>((float4*)xsum, nfeat4);
    k_xsum<<<agrid, 256>>>(x, ei, xsum, E, N);
    k_gemm_sage<<<ggrid, 256>>>(xsum, eagg, x, Wl1, P, Wr1,
                                bv0, bv1, inv, degc, h1, N, 1);

    // ---- layer 2 ----
    k_zero<<<zgrid, 256>>>((float4*)xsum, nfeat4);
    k_xsum<<<agrid, 256>>>(h1, ei, xsum, E, N);
    k_gemm_sage<<<ggrid, 256>>>(xsum, eagg, h1, Wl2, P + 4096, Wr2,
                                bv0 + 128, bv1 + 128, inv, degc, h2, N, 1);

    // ---- edge predictor (factored) ----
    // a = h2 @ Wp1[:128] + bp1 -> xsum buffer;  b = h2 @ Wp1[128:] -> h1 buffer
    k_gemm_sage<<<ggrid, 256>>>(h2, nullptr, nullptr, Wp1, nullptr, nullptr,
                                bp1, nullptr, nullptr, nullptr, xsum, N, 0);
    k_gemm_sage<<<ggrid, 256>>>(h2, nullptr, nullptr, Wp1 + 128 * 128, nullptr, nullptr,
                                nullptr, nullptr, nullptr, nullptr, h1, N, 0);

    k_edge_final<<<agrid, 256>>>(xsum, h1, ei, Wp2, bp2, out, E, N);
}

// round 5
// speedup vs baseline: 2.1504x; 1.2864x over previous
#include <cuda_runtime.h>
#include <cstdint>

#define N_NODES_MAX 100000
#define N_EDGES_MAX 600000

// Scratch (device globals)
__device__ __align__(16) float g_xsum[(size_t)N_NODES_MAX * 128];  // xsum; reused as 'a'
__device__ __align__(16) float g_h1  [(size_t)N_NODES_MAX * 128];  // layer-1 out; reused as 'b'
__device__ __align__(16) float g_h2  [(size_t)N_NODES_MAX * 128];  // layer-2 out
__device__ __align__(16) float g_eagg[(size_t)N_NODES_MAX * 32];   // sum of edge_attr per dst
__device__ __align__(16) float g_inv [N_NODES_MAX];                // 1/max(deg,1)
__device__ __align__(16) float g_degc[N_NODES_MAX];                // deg>0 ? 1 : 0
__device__ __align__(16) float g_P   [2 * 32 * 128];               // We_l @ Wl_l
__device__ __align__(16) float g_bv1 [2 * 128];                    // be_l @ Wl_l
__device__ __align__(16) float g_bv0 [2 * 128];                    // bl_l + br_l

// ---------------------------------------------------------------------------
// helpers
// ---------------------------------------------------------------------------
__device__ __forceinline__ void red_add_v4(float* p, float a, float b, float c, float d) {
    asm volatile("red.global.add.v4.f32 [%0], {%1, %2, %3, %4};"
                 :: "l"(p), "f"(a), "f"(b), "f"(c), "f"(d) : "memory");
}
__device__ __forceinline__ uint32_t to_tf32(float v) {
    uint32_t u;
    asm("cvt.rna.tf32.f32 %0, %1;" : "=r"(u) : "f"(v));
    return u;
}
__device__ __forceinline__ void mma_tf32(float c[4], const uint32_t a[4],
                                         uint32_t b0, uint32_t b1) {
    asm("mma.sync.aligned.m16n8k8.row.col.f32.tf32.tf32.f32 "
        "{%0,%1,%2,%3}, {%4,%5,%6,%7}, {%8,%9}, {%0,%1,%2,%3};"
        : "+f"(c[0]), "+f"(c[1]), "+f"(c[2]), "+f"(c[3])
        : "r"(a[0]), "r"(a[1]), "r"(a[2]), "r"(a[3]), "r"(b0), "r"(b1));
}

// ---------------------------------------------------------------------------
__global__ void k_zero(float4* __restrict__ p, int n4) {
    int i = blockIdx.x * blockDim.x + threadIdx.x;
    int stride = gridDim.x * blockDim.x;
    float4 z = make_float4(0.f, 0.f, 0.f, 0.f);
    for (; i < n4; i += stride) p[i] = z;
}

__global__ void k_deg_count(const int* __restrict__ ei, float* __restrict__ deg,
                            int E, int N) {
    int e = blockIdx.x * blockDim.x + threadIdx.x;
    if (e < E) {
        int d = ei[E + e];
        if ((unsigned)d < (unsigned)N) atomicAdd(&deg[d], 1.0f);
    }
}

__global__ void k_inv_transform(float* __restrict__ inv, float* __restrict__ degc, int N) {
    int i = blockIdx.x * blockDim.x + threadIdx.x;
    if (i < N) {
        float raw = inv[i];
        degc[i] = raw > 0.f ? 1.f : 0.f;
        inv[i] = 1.f / fmaxf(raw, 1.f);
    }
}

// ---------------------------------------------------------------------------
// eagg[dst] += edge_attr[e]  (32 floats). One warp handles 4 edges (8 lanes each).
// ---------------------------------------------------------------------------
__global__ void k_eagg(const int* __restrict__ ei, const float* __restrict__ ea,
                       float* __restrict__ eagg, int E, int N) {
    int lane = threadIdx.x & 31;
    int warp = (blockIdx.x * blockDim.x + threadIdx.x) >> 5;
    int nwarp = (gridDim.x * blockDim.x) >> 5;
    int sub = lane >> 3;
    int q   = lane & 7;

    const float4* ea4 = (const float4*)ea;
    for (int base = warp * 4; base < E; base += nwarp * 4) {
        int e = base + sub;
        if (e < E) {
            int d = ei[E + e];
            if ((unsigned)d < (unsigned)N) {
                float4 v = __ldg(ea4 + (size_t)e * 8 + q);
                red_add_v4(&eagg[(size_t)d * 32 + q * 4], v.x, v.y, v.z, v.w);
            }
        }
    }
}

// ---------------------------------------------------------------------------
// xsum[dst] += x[src]  (128 floats). One warp per edge, lane owns a float4.
// ---------------------------------------------------------------------------
__global__ void k_xsum(const float* __restrict__ x, const int* __restrict__ ei,
                       float* __restrict__ xsum, int E, int N) {
    int lane = threadIdx.x & 31;
    int warp = (blockIdx.x * blockDim.x + threadIdx.x) >> 5;
    int nwarp = (gridDim.x * blockDim.x) >> 5;

    const float4* x4 = (const float4*)x;
    for (int e = warp; e < E; e += nwarp) {
        int s = ei[e];
        int d = ei[E + e];
        if ((unsigned)s < (unsigned)N && (unsigned)d < (unsigned)N) {
            float4 v = __ldg(x4 + (size_t)s * 32 + lane);
            red_add_v4(&xsum[(size_t)d * 128 + lane * 4], v.x, v.y, v.z, v.w);
        }
    }
}

// ---------------------------------------------------------------------------
// Precompute P_l = We_l @ Wl_l, bv1_l = be_l @ Wl_l, bv0_l = bl_l + br_l.
// ---------------------------------------------------------------------------
__global__ void k_precompute(const float* We1, const float* be1, const float* Wl1,
                             const float* bl1, const float* br1,
                             const float* We2, const float* be2, const float* Wl2,
                             const float* bl2, const float* br2,
                             float* P, float* bv1, float* bv0) {
    int l = blockIdx.x;
    int j = threadIdx.x;
    const float* We = l ? We2 : We1;
    const float* be = l ? be2 : be1;
    const float* Wl = l ? Wl2 : Wl1;
    const float* bl = l ? bl2 : bl1;
    const float* br = l ? br2 : br1;

    for (int i = 0; i < 32; i++) {
        float acc = 0.f;
        for (int k = 0; k < 128; k++) acc = fmaf(We[i * 128 + k], Wl[k * 128 + j], acc);
        P[l * 4096 + i * 128 + j] = acc;
    }
    float a1 = 0.f;
    for (int k = 0; k < 128; k++) a1 = fmaf(be[k], Wl[k * 128 + j], a1);
    bv1[l * 128 + j] = a1;
    bv0[l * 128 + j] = bl[j] + br[j];
}

// ---------------------------------------------------------------------------
// Tensor-core SAGE node GEMM (tf32 mma.sync m16n8k8):
//   C = act( inv[m]*(A1 @ W1) + inv[m]*(A2 @ P) + B @ W2 + bv0 + degc[m]*bv1 )
// BM=128, BN=128, BK=16. 256 threads = 8 warps in 4x2 (m x n); warp = 32x64.
// ---------------------------------------------------------------------------
__global__ __launch_bounds__(256, 2)
void k_gemm_sage_tc(const float* __restrict__ A1,
                    const float* __restrict__ A2,
                    const float* __restrict__ B,
                    const float* __restrict__ W1,
                    const float* __restrict__ P,
                    const float* __restrict__ W2,
                    const float* __restrict__ bv0,
                    const float* __restrict__ bv1,
                    const float* __restrict__ inv,
                    const float* __restrict__ degc,
                    float* __restrict__ C,
                    int M, int relu) {
    __shared__ uint32_t As[16][136];   // A tile transposed [k][m], pad 136 -> conflict-free frags
    __shared__ uint32_t Ws[16][136];   // W tile [k][n]

    const int tid    = threadIdx.x;
    const int lane   = tid & 31;
    const int warp   = tid >> 5;
    const int gid    = lane >> 2;      // 0..7
    const int qid    = lane & 3;       // 0..3
    const int warp_m = warp >> 1;      // 0..3
    const int warp_n = warp & 1;       // 0..1
    const int m0     = blockIdx.x * 128;

    float c[2][8][4];
    #pragma unroll
    for (int mt = 0; mt < 2; mt++)
        #pragma unroll
        for (int nt = 0; nt < 8; nt++)
            #pragma unroll
            for (int i = 0; i < 4; i++) c[mt][nt][i] = 0.f;

    const int ktiles = (A2 != nullptr) ? 18 : 8;

    for (int kt = 0; kt < ktiles; kt++) {
        const float* Ain;
        const float* Win;
        int kb, astride;
        bool scaled;
        if (kt < 8)       { Ain = A1; Win = W1; kb = kt * 16;        astride = 128; scaled = (inv != nullptr); }
        else if (kt < 10) { Ain = A2; Win = P;  kb = (kt - 8) * 16;  astride = 32;  scaled = (inv != nullptr); }
        else              { Ain = B;  Win = W2; kb = (kt - 10) * 16; astride = 128; scaled = false; }

        // A tile: 128 rows x 16 k, transposed into As[k][m] (tf32)
        #pragma unroll
        for (int i = 0; i < 8; i++) {
            int lin = tid + i * 256;       // 0..2047
            int m = lin >> 4;
            int k = lin & 15;
            int gm = m0 + m;
            float v = 0.f;
            if (gm < M) {
                v = Ain[(size_t)gm * astride + kb + k];
                if (scaled) v *= inv[gm];
            }
            As[k][m] = to_tf32(v);
        }
        // W tile: 16 k x 128 n (tf32)
        #pragma unroll
        for (int i = 0; i < 8; i++) {
            int lin = tid + i * 256;
            int k = lin >> 7;
            int j = lin & 127;
            Ws[k][j] = to_tf32(Win[(size_t)(kb + k) * 128 + j]);
        }
        __syncthreads();

        #pragma unroll
        for (int ks = 0; ks < 2; ks++) {
            const int k8 = ks * 8;
            uint32_t a[2][4];
            #pragma unroll
            for (int mt = 0; mt < 2; mt++) {
                int row = warp_m * 32 + mt * 16 + gid;
                a[mt][0] = As[k8 + qid][row];
                a[mt][1] = As[k8 + qid][row + 8];
                a[mt][2] = As[k8 + qid + 4][row];
                a[mt][3] = As[k8 + qid + 4][row + 8];
            }
            #pragma unroll
            for (int nt = 0; nt < 8; nt++) {
                int col = warp_n * 64 + nt * 8 + gid;
                uint32_t b0 = Ws[k8 + qid][col];
                uint32_t b1 = Ws[k8 + qid + 4][col];
                mma_tf32(c[0][nt], a[0], b0, b1);
                mma_tf32(c[1][nt], a[1], b0, b1);
            }
        }
        __syncthreads();
    }

    // epilogue: thread owns cols j0=warp_n*64+nt*8+qid*2 (+1), rows r0=.., r0+8
    #pragma unroll
    for (int mt = 0; mt < 2; mt++) {
        int rbase = m0 + warp_m * 32 + mt * 16 + gid;
        #pragma unroll
        for (int h = 0; h < 2; h++) {
            int r = rbase + h * 8;
            if (r >= M) continue;
            float coef = (bv1 && degc) ? degc[r] : 0.f;
            #pragma unroll
            for (int nt = 0; nt < 8; nt++) {
                int j = warp_n * 64 + nt * 8 + qid * 2;
                float v0 = c[mt][nt][h * 2 + 0];
                float v1 = c[mt][nt][h * 2 + 1];
                if (bv0) { v0 += bv0[j]; v1 += bv0[j + 1]; }
                if (bv1) { v0 += coef * bv1[j]; v1 += coef * bv1[j + 1]; }
                if (relu) { v0 = fmaxf(v0, 0.f); v1 = fmaxf(v1, 0.f); }
                *(float2*)&C[(size_t)r * 128 + j] = make_float2(v0, v1);
            }
        }
    }
}

// ---------------------------------------------------------------------------
// Final edge predictor: out[e] = relu(a[src] + b[dst]) @ Wp2 + bp2
// ---------------------------------------------------------------------------
__global__ void k_edge_final(const float* __restrict__ a,
                             const float* __restrict__ b,
                             const int* __restrict__ ei,
                             const float* __restrict__ Wp2,
                             const float* __restrict__ bp2,
                             float* __restrict__ out,
                             int E, int N) {
    int lane = threadIdx.x & 31;
    int warp = (blockIdx.x * blockDim.x + threadIdx.x) >> 5;
    int nwarp = (gridDim.x * blockDim.x) >> 5;

    float4 w01 = ((const float4*)Wp2)[lane * 2];
    float4 w23 = ((const float4*)Wp2)[lane * 2 + 1];
    float b0 = bp2[0], b1 = bp2[1];

    for (int e = warp; e < E; e += nwarp) {
        int s = ei[e];
        int d = ei[E + e];
        if ((unsigned)s >= (unsigned)N || (unsigned)d >= (unsigned)N) continue;
        float4 av = __ldg((const float4*)a + (size_t)s * 32 + lane);
        float4 bv = __ldg((const float4*)b + (size_t)d * 32 + lane);
        float z0 = fmaxf(av.x + bv.x, 0.f);
        float z1 = fmaxf(av.y + bv.y, 0.f);
        float z2 = fmaxf(av.z + bv.z, 0.f);
        float z3 = fmaxf(av.w + bv.w, 0.f);
        float o0 = z0 * w01.x + z1 * w01.z + z2 * w23.x + z3 * w23.z;
        float o1 = z0 * w01.y + z1 * w01.w + z2 * w23.y + z3 * w23.w;
        #pragma unroll
        for (int off = 16; off > 0; off >>= 1) {
            o0 += __shfl_xor_sync(0xffffffffu, o0, off);
            o1 += __shfl_xor_sync(0xffffffffu, o1, off);
        }
        if (lane == 0) {
            float2 r = make_float2(o0 + b0, o1 + b1);
            *(float2*)&out[(size_t)e * 2] = r;
        }
    }
}

// ---------------------------------------------------------------------------
extern "C" void kernel_launch(void* const* d_in, const int* in_sizes, int n_in,
                              void* d_out, int out_size) {
    const float* x    = (const float*)d_in[0];
    const int*   ei   = (const int*)d_in[1];     // int32
    const float* ea   = (const float*)d_in[2];
    const float* We1  = (const float*)d_in[3];
    const float* be1  = (const float*)d_in[4];
    const float* Wl1  = (const float*)d_in[5];
    const float* bl1  = (const float*)d_in[6];
    const float* Wr1  = (const float*)d_in[7];
    const float* br1  = (const float*)d_in[8];
    const float* We2  = (const float*)d_in[9];
    const float* be2  = (const float*)d_in[10];
    const float* Wl2  = (const float*)d_in[11];
    const float* bl2  = (const float*)d_in[12];
    const float* Wr2  = (const float*)d_in[13];
    const float* br2  = (const float*)d_in[14];
    const float* Wp1  = (const float*)d_in[15];
    const float* bp1  = (const float*)d_in[16];
    const float* Wp2  = (const float*)d_in[17];
    const float* bp2  = (const float*)d_in[18];
    float*       out  = (float*)d_out;

    const int N = in_sizes[0] / 128;
    const int E = in_sizes[2] / 32;

    float *xsum, *h1, *h2, *eagg, *inv, *degc, *P, *bv1, *bv0;
    cudaGetSymbolAddress((void**)&xsum, g_xsum);
    cudaGetSymbolAddress((void**)&h1,   g_h1);
    cudaGetSymbolAddress((void**)&h2,   g_h2);
    cudaGetSymbolAddress((void**)&eagg, g_eagg);
    cudaGetSymbolAddress((void**)&inv,  g_inv);
    cudaGetSymbolAddress((void**)&degc, g_degc);
    cudaGetSymbolAddress((void**)&P,    g_P);
    cudaGetSymbolAddress((void**)&bv1,  g_bv1);
    cudaGetSymbolAddress((void**)&bv0,  g_bv0);

    const int nfeat4 = (N * 128) / 4;
    const int zgrid  = (nfeat4 + 255) / 256;
    const int agrid  = 2368;
    const int ggrid  = (N + 127) / 128;

    // degrees
    k_zero<<<(N / 4 + 255) / 256, 256>>>((float4*)inv, N / 4);
    k_deg_count<<<(E + 255) / 256, 256>>>(ei, inv, E, N);
    k_inv_transform<<<(N + 255) / 256, 256>>>(inv, degc, N);

    // edge-attr aggregation (once — shared by both layers)
    k_zero<<<(N * 32 / 4 + 255) / 256, 256>>>((float4*)eagg, N * 32 / 4);
    k_eagg<<<agrid, 256>>>(ei, ea, eagg, E, N);

    // weight precompute
    k_precompute<<<2, 128>>>(We1, be1, Wl1, bl1, br1, We2, be2, Wl2, bl2, br2, P, bv1, bv0);

    // ---- layer 1 ----
    k_zero<<<zgrid, 256>>>((float4*)xsum, nfeat4);
    k_xsum<<<agrid, 256>>>(x, ei, xsum, E, N);
    k_gemm_sage_tc<<<ggrid, 256>>>(xsum, eagg, x, Wl1, P, Wr1,
                                   bv0, bv1, inv, degc, h1, N, 1);

    // ---- layer 2 ----
    k_zero<<<zgrid, 256>>>((float4*)xsum, nfeat4);
    k_xsum<<<agrid, 256>>>(h1, ei, xsum, E, N);
    k_gemm_sage_tc<<<ggrid, 256>>>(xsum, eagg, h1, Wl2, P + 4096, Wr2,
                                   bv0 + 128, bv1 + 128, inv, degc, h2, N, 1);

    // ---- edge predictor (factored) ----
    k_gemm_sage_tc<<<ggrid, 256>>>(h2, nullptr, nullptr, Wp1, nullptr, nullptr,
                                   bp1, nullptr, nullptr, nullptr, xsum, N, 0);
    k_gemm_sage_tc<<<ggrid, 256>>>(h2, nullptr, nullptr, Wp1 + 128 * 128, nullptr, nullptr,
                                   nullptr, nullptr, nullptr, nullptr, h1, N, 0);

    k_edge_final<<<agrid, 256>>>(xsum, h1, ei, Wp2, bp2, out, E, N);
}

// round 6
// speedup vs baseline: 2.2884x; 1.0642x over previous
#include <cuda_runtime.h>
#include <cstdint>

#define N_NODES_MAX 100000
#define N_EDGES_MAX 600000

// Scratch (device globals)
__device__ __align__(16) float g_xsum[(size_t)N_NODES_MAX * 128];  // xsum; reused as 'a'
__device__ __align__(16) float g_h1  [(size_t)N_NODES_MAX * 128];  // layer-1 out; reused as 'b'
__device__ __align__(16) float g_h2  [(size_t)N_NODES_MAX * 128];  // layer-2 out
__device__ __align__(16) float g_eagg[(size_t)N_NODES_MAX * 32];   // sum of edge_attr per dst
__device__ __align__(16) float g_inv [N_NODES_MAX];                // 1/max(deg,1)
__device__ __align__(16) float g_degc[N_NODES_MAX];                // deg>0 ? 1 : 0
__device__ __align__(16) float g_P   [2 * 32 * 128];               // We_l @ Wl_l
__device__ __align__(16) float g_bv1 [2 * 128];                    // be_l @ Wl_l
__device__ __align__(16) float g_bv0 [2 * 128];                    // bl_l + br_l
// CSR (built per launch)
__device__ int g_rowptr[N_NODES_MAX + 1];
__device__ int g_cnt   [N_NODES_MAX];
__device__ int g_bsum  [1024];
__device__ int g_boff  [1024];
__device__ int g_csr_src[N_EDGES_MAX];
__device__ int g_csr_eid[N_EDGES_MAX];

// ---------------------------------------------------------------------------
// helpers
// ---------------------------------------------------------------------------
__device__ __forceinline__ uint32_t to_tf32(float v) {
    uint32_t u;
    asm("cvt.rna.tf32.f32 %0, %1;" : "=r"(u) : "f"(v));
    return u;
}
__device__ __forceinline__ void mma_tf32(float c[4], const uint32_t a[4],
                                         uint32_t b0, uint32_t b1) {
    asm("mma.sync.aligned.m16n8k8.row.col.f32.tf32.tf32.f32 "
        "{%0,%1,%2,%3}, {%4,%5,%6,%7}, {%8,%9}, {%0,%1,%2,%3};"
        : "+f"(c[0]), "+f"(c[1]), "+f"(c[2]), "+f"(c[3])
        : "r"(a[0]), "r"(a[1]), "r"(a[2]), "r"(a[3]), "r"(b0), "r"(b1));
}

// ---------------------------------------------------------------------------
// CSR build
// ---------------------------------------------------------------------------
__global__ void k_zero_int(int* __restrict__ p, int n) {
    int i = blockIdx.x * blockDim.x + threadIdx.x;
    if (i < n) p[i] = 0;
}

__global__ void k_hist(const int* __restrict__ ei, int* __restrict__ cnt, int E, int N) {
    int e = blockIdx.x * blockDim.x + threadIdx.x;
    if (e < E) {
        int d = ei[E + e];
        if ((unsigned)d < (unsigned)N) atomicAdd(&cnt[d], 1);
    }
}

// block-wise inclusive scan of cnt -> rowptr[i+1]; block totals -> bsum
__global__ void k_scan1(const int* __restrict__ cnt, int* __restrict__ rowptr,
                        int* __restrict__ bsum, int N) {
    __shared__ int sm[512];
    int t = threadIdx.x, b = blockIdx.x, i = b * 512 + t;
    int v = (i < N) ? cnt[i] : 0;
    sm[t] = v;
    __syncthreads();
    #pragma unroll
    for (int off = 1; off < 512; off <<= 1) {
        int add = (t >= off) ? sm[t - off] : 0;
        __syncthreads();
        sm[t] += add;
        __syncthreads();
    }
    if (i < N) rowptr[i + 1] = sm[t];
    if (t == 511) bsum[b] = sm[511];
}

// exclusive scan of bsum (nb <= 1024) -> boff
__global__ void k_scan2(const int* __restrict__ bsum, int* __restrict__ boff, int nb) {
    __shared__ int sm[1024];
    int t = threadIdx.x;
    sm[t] = (t < nb) ? bsum[t] : 0;
    __syncthreads();
    #pragma unroll
    for (int off = 1; off < 1024; off <<= 1) {
        int add = (t >= off) ? sm[t - off] : 0;
        __syncthreads();
        sm[t] += add;
        __syncthreads();
    }
    if (t < nb) boff[t] = (t == 0) ? 0 : sm[t - 1];
}

// add block offsets; zero cnt for reuse as fill cursor; set rowptr[0]
__global__ void k_scan3(int* __restrict__ rowptr, const int* __restrict__ boff,
                        int* __restrict__ cnt, int N) {
    int t = threadIdx.x, b = blockIdx.x, i = b * 512 + t;
    if (i < N) {
        rowptr[i + 1] += boff[b];
        cnt[i] = 0;
        if (i == 0) rowptr[0] = 0;
    }
}

__global__ void k_invdeg(const int* __restrict__ rowptr, float* __restrict__ inv,
                         float* __restrict__ degc, int N) {
    int i = blockIdx.x * blockDim.x + threadIdx.x;
    if (i < N) {
        int deg = rowptr[i + 1] - rowptr[i];
        degc[i] = deg > 0 ? 1.f : 0.f;
        inv[i] = 1.f / fmaxf((float)deg, 1.f);
    }
}

__global__ void k_fill(const int* __restrict__ ei, const int* __restrict__ rowptr,
                       int* __restrict__ cnt, int* __restrict__ csr_src,
                       int* __restrict__ csr_eid, int E, int N) {
    int e = blockIdx.x * blockDim.x + threadIdx.x;
    if (e < E) {
        int s = ei[e];
        int d = ei[E + e];
        if ((unsigned)d < (unsigned)N) {
            int pos = rowptr[d] + atomicAdd(&cnt[d], 1);
            csr_src[pos] = s;
            csr_eid[pos] = e;
        }
    }
}

// ---------------------------------------------------------------------------
// CSR aggregation: one warp per node, register accumulate, single write.
// Layer 1 also sums edge_attr (eagg).
// ---------------------------------------------------------------------------
__global__ void k_agg_l1(const float* __restrict__ x, const float* __restrict__ ea,
                         const int* __restrict__ rowptr,
                         const int* __restrict__ csr_src, const int* __restrict__ csr_eid,
                         float* __restrict__ xsum, float* __restrict__ eagg, int N) {
    int lane = threadIdx.x & 31;
    int n = (blockIdx.x * blockDim.x + threadIdx.x) >> 5;
    if (n >= N) return;
    int beg = rowptr[n], end = rowptr[n + 1];
    const float4* x4 = (const float4*)x;
    float4 acc = make_float4(0.f, 0.f, 0.f, 0.f);
    float eacc = 0.f;
    int i = beg;
    for (; i + 1 < end; i += 2) {
        int s0 = __ldg(&csr_src[i]),     e0 = __ldg(&csr_eid[i]);
        int s1 = __ldg(&csr_src[i + 1]), e1 = __ldg(&csr_eid[i + 1]);
        float4 v0 = __ldg(x4 + (size_t)s0 * 32 + lane);
        float4 v1 = __ldg(x4 + (size_t)s1 * 32 + lane);
        float w0 = __ldg(&ea[(size_t)e0 * 32 + lane]);
        float w1 = __ldg(&ea[(size_t)e1 * 32 + lane]);
        acc.x += v0.x + v1.x; acc.y += v0.y + v1.y;
        acc.z += v0.z + v1.z; acc.w += v0.w + v1.w;
        eacc += w0 + w1;
    }
    if (i < end) {
        int s0 = __ldg(&csr_src[i]), e0 = __ldg(&csr_eid[i]);
        float4 v0 = __ldg(x4 + (size_t)s0 * 32 + lane);
        float w0 = __ldg(&ea[(size_t)e0 * 32 + lane]);
        acc.x += v0.x; acc.y += v0.y; acc.z += v0.z; acc.w += v0.w;
        eacc += w0;
    }
    ((float4*)xsum)[(size_t)n * 32 + lane] = acc;
    eagg[(size_t)n * 32 + lane] = eacc;
}

__global__ void k_agg_l2(const float* __restrict__ x,
                         const int* __restrict__ rowptr,
                         const int* __restrict__ csr_src,
                         float* __restrict__ xsum, int N) {
    int lane = threadIdx.x & 31;
    int n = (blockIdx.x * blockDim.x + threadIdx.x) >> 5;
    if (n >= N) return;
    int beg = rowptr[n], end = rowptr[n + 1];
    const float4* x4 = (const float4*)x;
    float4 acc = make_float4(0.f, 0.f, 0.f, 0.f);
    int i = beg;
    for (; i + 1 < end; i += 2) {
        int s0 = __ldg(&csr_src[i]);
        int s1 = __ldg(&csr_src[i + 1]);
        float4 v0 = __ldg(x4 + (size_t)s0 * 32 + lane);
        float4 v1 = __ldg(x4 + (size_t)s1 * 32 + lane);
        acc.x += v0.x + v1.x; acc.y += v0.y + v1.y;
        acc.z += v0.z + v1.z; acc.w += v0.w + v1.w;
    }
    if (i < end) {
        int s0 = __ldg(&csr_src[i]);
        float4 v0 = __ldg(x4 + (size_t)s0 * 32 + lane);
        acc.x += v0.x; acc.y += v0.y; acc.z += v0.z; acc.w += v0.w;
    }
    ((float4*)xsum)[(size_t)n * 32 + lane] = acc;
}

// ---------------------------------------------------------------------------
// Precompute P_l = We_l @ Wl_l, bv1_l = be_l @ Wl_l, bv0_l = bl_l + br_l.
// ---------------------------------------------------------------------------
__global__ void k_precompute(const float* We1, const float* be1, const float* Wl1,
                             const float* bl1, const float* br1,
                             const float* We2, const float* be2, const float* Wl2,
                             const float* bl2, const float* br2,
                             float* P, float* bv1, float* bv0) {
    int l = blockIdx.x;
    int j = threadIdx.x;
    const float* We = l ? We2 : We1;
    const float* be = l ? be2 : be1;
    const float* Wl = l ? Wl2 : Wl1;
    const float* bl = l ? bl2 : bl1;
    const float* br = l ? br2 : br1;

    for (int i = 0; i < 32; i++) {
        float acc = 0.f;
        for (int k = 0; k < 128; k++) acc = fmaf(We[i * 128 + k], Wl[k * 128 + j], acc);
        P[l * 4096 + i * 128 + j] = acc;
    }
    float a1 = 0.f;
    for (int k = 0; k < 128; k++) a1 = fmaf(be[k], Wl[k * 128 + j], a1);
    bv1[l * 128 + j] = a1;
    bv0[l * 128 + j] = bl[j] + br[j];
}

// ---------------------------------------------------------------------------
// Tensor-core SAGE node GEMM (tf32 mma.sync m16n8k8):
//   C = act( inv[m]*(A1 @ W1) + inv[m]*(A2 @ P) + B @ W2 + bv0 + degc[m]*bv1 )
// BM=128, BN=128, BK=16. 256 threads = 8 warps in 4x2 (m x n); warp = 32x64.
// ---------------------------------------------------------------------------
__global__ __launch_bounds__(256, 2)
void k_gemm_sage_tc(const float* __restrict__ A1,
                    const float* __restrict__ A2,
                    const float* __restrict__ B,
                    const float* __restrict__ W1,
                    const float* __restrict__ P,
                    const float* __restrict__ W2,
                    const float* __restrict__ bv0,
                    const float* __restrict__ bv1,
                    const float* __restrict__ inv,
                    const float* __restrict__ degc,
                    float* __restrict__ C,
                    int M, int relu) {
    __shared__ uint32_t As[16][136];
    __shared__ uint32_t Ws[16][136];

    const int tid    = threadIdx.x;
    const int lane   = tid & 31;
    const int warp   = tid >> 5;
    const int gid    = lane >> 2;
    const int qid    = lane & 3;
    const int warp_m = warp >> 1;
    const int warp_n = warp & 1;
    const int m0     = blockIdx.x * 128;

    float c[2][8][4];
    #pragma unroll
    for (int mt = 0; mt < 2; mt++)
        #pragma unroll
        for (int nt = 0; nt < 8; nt++)
            #pragma unroll
            for (int i = 0; i < 4; i++) c[mt][nt][i] = 0.f;

    const int ktiles = (A2 != nullptr) ? 18 : 8;

    for (int kt = 0; kt < ktiles; kt++) {
        const float* Ain;
        const float* Win;
        int kb, astride;
        bool scaled;
        if (kt < 8)       { Ain = A1; Win = W1; kb = kt * 16;        astride = 128; scaled = (inv != nullptr); }
        else if (kt < 10) { Ain = A2; Win = P;  kb = (kt - 8) * 16;  astride = 32;  scaled = (inv != nullptr); }
        else              { Ain = B;  Win = W2; kb = (kt - 10) * 16; astride = 128; scaled = false; }

        #pragma unroll
        for (int i = 0; i < 8; i++) {
            int lin = tid + i * 256;
            int m = lin >> 4;
            int k = lin & 15;
            int gm = m0 + m;
            float v = 0.f;
            if (gm < M) {
                v = Ain[(size_t)gm * astride + kb + k];
                if (scaled) v *= inv[gm];
            }
            As[k][m] = to_tf32(v);
        }
        #pragma unroll
        for (int i = 0; i < 8; i++) {
            int lin = tid + i * 256;
            int k = lin >> 7;
            int j = lin & 127;
            Ws[k][j] = to_tf32(Win[(size_t)(kb + k) * 128 + j]);
        }
        __syncthreads();

        #pragma unroll
        for (int ks = 0; ks < 2; ks++) {
            const int k8 = ks * 8;
            uint32_t a[2][4];
            #pragma unroll
            for (int mt = 0; mt < 2; mt++) {
                int row = warp_m * 32 + mt * 16 + gid;
                a[mt][0] = As[k8 + qid][row];
                a[mt][1] = As[k8 + qid][row + 8];
                a[mt][2] = As[k8 + qid + 4][row];
                a[mt][3] = As[k8 + qid + 4][row + 8];
            }
            #pragma unroll
            for (int nt = 0; nt < 8; nt++) {
                int col = warp_n * 64 + nt * 8 + gid;
                uint32_t b0 = Ws[k8 + qid][col];
                uint32_t b1 = Ws[k8 + qid + 4][col];
                mma_tf32(c[0][nt], a[0], b0, b1);
                mma_tf32(c[1][nt], a[1], b0, b1);
            }
        }
        __syncthreads();
    }

    #pragma unroll
    for (int mt = 0; mt < 2; mt++) {
        int rbase = m0 + warp_m * 32 + mt * 16 + gid;
        #pragma unroll
        for (int h = 0; h < 2; h++) {
            int r = rbase + h * 8;
            if (r >= M) continue;
            float coef = (bv1 && degc) ? degc[r] : 0.f;
            #pragma unroll
            for (int nt = 0; nt < 8; nt++) {
                int j = warp_n * 64 + nt * 8 + qid * 2;
                float v0 = c[mt][nt][h * 2 + 0];
                float v1 = c[mt][nt][h * 2 + 1];
                if (bv0) { v0 += bv0[j]; v1 += bv0[j + 1]; }
                if (bv1) { v0 += coef * bv1[j]; v1 += coef * bv1[j + 1]; }
                if (relu) { v0 = fmaxf(v0, 0.f); v1 = fmaxf(v1, 0.f); }
                *(float2*)&C[(size_t)r * 128 + j] = make_float2(v0, v1);
            }
        }
    }
}

// ---------------------------------------------------------------------------
// Final edge predictor: out[e] = relu(a[src] + b[dst]) @ Wp2 + bp2
// ---------------------------------------------------------------------------
__global__ void k_edge_final(const float* __restrict__ a,
                             const float* __restrict__ b,
                             const int* __restrict__ ei,
                             const float* __restrict__ Wp2,
                             const float* __restrict__ bp2,
                             float* __restrict__ out,
                             int E, int N) {
    int lane = threadIdx.x & 31;
    int warp = (blockIdx.x * blockDim.x + threadIdx.x) >> 5;
    int nwarp = (gridDim.x * blockDim.x) >> 5;

    float4 w01 = ((const float4*)Wp2)[lane * 2];
    float4 w23 = ((const float4*)Wp2)[lane * 2 + 1];
    float b0 = bp2[0], b1 = bp2[1];

    for (int e = warp; e < E; e += nwarp) {
        int s = ei[e];
        int d = ei[E + e];
        if ((unsigned)s >= (unsigned)N || (unsigned)d >= (unsigned)N) continue;
        float4 av = __ldg((const float4*)a + (size_t)s * 32 + lane);
        float4 bv = __ldg((const float4*)b + (size_t)d * 32 + lane);
        float z0 = fmaxf(av.x + bv.x, 0.f);
        float z1 = fmaxf(av.y + bv.y, 0.f);
        float z2 = fmaxf(av.z + bv.z, 0.f);
        float z3 = fmaxf(av.w + bv.w, 0.f);
        float o0 = z0 * w01.x + z1 * w01.z + z2 * w23.x + z3 * w23.z;
        float o1 = z0 * w01.y + z1 * w01.w + z2 * w23.y + z3 * w23.w;
        #pragma unroll
        for (int off = 16; off > 0; off >>= 1) {
            o0 += __shfl_xor_sync(0xffffffffu, o0, off);
            o1 += __shfl_xor_sync(0xffffffffu, o1, off);
        }
        if (lane == 0) {
            float2 r = make_float2(o0 + b0, o1 + b1);
            *(float2*)&out[(size_t)e * 2] = r;
        }
    }
}

// ---------------------------------------------------------------------------
extern "C" void kernel_launch(void* const* d_in, const int* in_sizes, int n_in,
                              void* d_out, int out_size) {
    const float* x    = (const float*)d_in[0];
    const int*   ei   = (const int*)d_in[1];     // int32
    const float* ea   = (const float*)d_in[2];
    const float* We1  = (const float*)d_in[3];
    const float* be1  = (const float*)d_in[4];
    const float* Wl1  = (const float*)d_in[5];
    const float* bl1  = (const float*)d_in[6];
    const float* Wr1  = (const float*)d_in[7];
    const float* br1  = (const float*)d_in[8];
    const float* We2  = (const float*)d_in[9];
    const float* be2  = (const float*)d_in[10];
    const float* Wl2  = (const float*)d_in[11];
    const float* bl2  = (const float*)d_in[12];
    const float* Wr2  = (const float*)d_in[13];
    const float* br2  = (const float*)d_in[14];
    const float* Wp1  = (const float*)d_in[15];
    const float* bp1  = (const float*)d_in[16];
    const float* Wp2  = (const float*)d_in[17];
    const float* bp2  = (const float*)d_in[18];
    float*       out  = (float*)d_out;

    const int N = in_sizes[0] / 128;
    const int E = in_sizes[2] / 32;

    float *xsum, *h1, *h2, *eagg, *inv, *degc, *P, *bv1, *bv0;
    int *rowptr, *cnt, *bsum, *boff, *csr_src, *csr_eid;
    cudaGetSymbolAddress((void**)&xsum, g_xsum);
    cudaGetSymbolAddress((void**)&h1,   g_h1);
    cudaGetSymbolAddress((void**)&h2,   g_h2);
    cudaGetSymbolAddress((void**)&eagg, g_eagg);
    cudaGetSymbolAddress((void**)&inv,  g_inv);
    cudaGetSymbolAddress((void**)&degc, g_degc);
    cudaGetSymbolAddress((void**)&P,    g_P);
    cudaGetSymbolAddress((void**)&bv1,  g_bv1);
    cudaGetSymbolAddress((void**)&bv0,  g_bv0);
    cudaGetSymbolAddress((void**)&rowptr, g_rowptr);
    cudaGetSymbolAddress((void**)&cnt,    g_cnt);
    cudaGetSymbolAddress((void**)&bsum,   g_bsum);
    cudaGetSymbolAddress((void**)&boff,   g_boff);
    cudaGetSymbolAddress((void**)&csr_src, g_csr_src);
    cudaGetSymbolAddress((void**)&csr_eid, g_csr_eid);

    const int nb    = (N + 511) / 512;           // scan blocks
    const int ggrid = (N + 127) / 128;           // GEMM grid
    const int agrid = (N + 7) / 8;               // warp-per-node grid (256 thr)
    const int egrid = 2368;                      // edge_final grid-stride

    // ---- CSR build ----
    k_zero_int<<<(N + 255) / 256, 256>>>(cnt, N);
    k_hist<<<(E + 255) / 256, 256>>>(ei, cnt, E, N);
    k_scan1<<<nb, 512>>>(cnt, rowptr, bsum, N);
    k_scan2<<<1, 1024>>>(bsum, boff, nb);
    k_scan3<<<nb, 512>>>(rowptr, boff, cnt, N);
    k_invdeg<<<(N + 255) / 256, 256>>>(rowptr, inv, degc, N);
    k_fill<<<(E + 255) / 256, 256>>>(ei, rowptr, cnt, csr_src, csr_eid, E, N);

    // weight precompute (independent — overlaps nothing but cheap)
    k_precompute<<<2, 128>>>(We1, be1, Wl1, bl1, br1, We2, be2, Wl2, bl2, br2, P, bv1, bv0);

    // ---- layer 1 ----
    k_agg_l1<<<agrid, 256>>>(x, ea, rowptr, csr_src, csr_eid, xsum, eagg, N);
    k_gemm_sage_tc<<<ggrid, 256>>>(xsum, eagg, x, Wl1, P, Wr1,
                                   bv0, bv1, inv, degc, h1, N, 1);

    // ---- layer 2 ----
    k_agg_l2<<<agrid, 256>>>(h1, rowptr, csr_src, xsum, N);
    k_gemm_sage_tc<<<ggrid, 256>>>(xsum, eagg, h1, Wl2, P + 4096, Wr2,
                                   bv0 + 128, bv1 + 128, inv, degc, h2, N, 1);

    // ---- edge predictor (factored) ----
    k_gemm_sage_tc<<<ggrid, 256>>>(h2, nullptr, nullptr, Wp1, nullptr, nullptr,
                                   bp1, nullptr, nullptr, nullptr, xsum, N, 0);
    k_gemm_sage_tc<<<ggrid, 256>>>(h2, nullptr, nullptr, Wp1 + 128 * 128, nullptr, nullptr,
                                   nullptr, nullptr, nullptr, nullptr, h1, N, 0);

    k_edge_final<<<egrid, 256>>>(xsum, h1, ei, Wp2, bp2, out, E, N);
}